// round 1
// baseline (speedup 1.0000x reference)
#include <cuda_runtime.h>
#include <math.h>

// ---------------------------------------------------------------------------
// RWKV-v4 block: B=4, T=4096, C=2048, A=2048, FF=8192
// Structure:
//   K1: LN1 + time-mix        -> xk, xv, xr
//   G1-3: k/v/sigmoid(r) GEMMs (tf32 mma.sync, NT)
//   K2: WKV scan (per-channel recurrence), writes sigmoid(r)*y and new state
//   G4: x_att = x + (sr*y) @ Wo^T   (residual fused in epilogue)
//   K3: LN2 + channel-mix     -> xkf, xrf
//   G5: kf = relu(xkf @ Wk_f^T)^2   (fused epilogue)
//   G6: rr = sigmoid(xrf @ Wr_f^T)
//   G7: x_out = x_att + rr * (kf @ Wv_f^T)  (fused epilogue)
// ---------------------------------------------------------------------------

#define B_  4
#define T_  4096
#define C_  2048
#define A_  2048
#define FF_ 8192

#define BTCll ((long long)B_ * T_ * C_)   // 33,554,432
#define BTFll ((long long)B_ * T_ * FF_)  // 134,217,728

// Scratch: xk,xv,xr,k,v,sr,sy (7 * BTC) + kf (BTF) = ~1.48 GB
__device__ float g_buf[7LL * 33554432LL + 134217728LL];

// ---------------------------------------------------------------------------
// Block reduce of 4 values simultaneously (256 threads)
// ---------------------------------------------------------------------------
__device__ __forceinline__ void blockReduce4(float& a, float& b, float& c, float& d) {
    #pragma unroll
    for (int o = 16; o > 0; o >>= 1) {
        a += __shfl_down_sync(0xffffffffu, a, o);
        b += __shfl_down_sync(0xffffffffu, b, o);
        c += __shfl_down_sync(0xffffffffu, c, o);
        d += __shfl_down_sync(0xffffffffu, d, o);
    }
    __shared__ float sh[8][4];
    int w = threadIdx.x >> 5, l = threadIdx.x & 31;
    if (l == 0) { sh[w][0] = a; sh[w][1] = b; sh[w][2] = c; sh[w][3] = d; }
    __syncthreads();
    if (threadIdx.x == 0) {
        float ta = 0, tb = 0, tc = 0, td = 0;
        #pragma unroll
        for (int i = 0; i < 8; i++) { ta += sh[i][0]; tb += sh[i][1]; tc += sh[i][2]; td += sh[i][3]; }
        sh[0][0] = ta; sh[0][1] = tb; sh[0][2] = tc; sh[0][3] = td;
    }
    __syncthreads();
    a = sh[0][0]; b = sh[0][1]; c = sh[0][2]; d = sh[0][3];
}

// ---------------------------------------------------------------------------
// LayerNorm + time/channel shift mix. One block per (b,t) row.
// Re-normalizes row t-1 in-block (never materializes xn), so the only
// traffic is x (and x[t-1], L2-resident) in and the mixed outputs out.
// t==0 uses the raw shift_in row. t==T-1 writes shift_out = xn row.
// ---------------------------------------------------------------------------
template <int NMIX>
__global__ __launch_bounds__(256) void ln_mix_kernel(
    const float* __restrict__ x, const float* __restrict__ shift_in,
    const float* __restrict__ gw, const float* __restrict__ bw,
    const float* __restrict__ m0, const float* __restrict__ m1, const float* __restrict__ m2,
    float* __restrict__ o0, float* __restrict__ o1, float* __restrict__ o2,
    float* __restrict__ shift_out)
{
    const int bt = blockIdx.x;
    const int b = bt / T_, t = bt % T_;
    const int tid = threadIdx.x;
    const float* xr = x + (long long)bt * C_;

    float cur[8], prv[8];
    float s1 = 0.f, s2 = 0.f, p1 = 0.f, p2 = 0.f;
    #pragma unroll
    for (int i = 0; i < 8; i++) {
        int c = tid + i * 256;
        float v = xr[c];
        cur[i] = v; s1 += v; s2 += v * v;
        if (t > 0) {
            float w = xr[c - C_];
            prv[i] = w; p1 += w; p2 += w * w;
        } else {
            prv[i] = 0.f;
        }
    }
    blockReduce4(s1, s2, p1, p2);
    const float inv = 1.f / (float)C_;
    float mu = s1 * inv;
    float var = s2 * inv - mu * mu;
    float rs = rsqrtf(var + 1e-5f);
    float mup = 0.f, rsp = 0.f;
    if (t > 0) {
        mup = p1 * inv;
        float vp = p2 * inv - mup * mup;
        rsp = rsqrtf(vp + 1e-5f);
    }
    long long o = (long long)bt * C_;
    #pragma unroll
    for (int i = 0; i < 8; i++) {
        int c = tid + i * 256;
        float gg = gw[c], bb = bw[c];
        float xn = (cur[i] - mu) * rs * gg + bb;
        float xx = (t > 0) ? ((prv[i] - mup) * rsp * gg + bb)
                           : shift_in[(long long)b * C_ + c];
        float a0 = m0[c]; o0[o + c] = xn * a0 + xx * (1.f - a0);
        float a1 = m1[c]; o1[o + c] = xn * a1 + xx * (1.f - a1);
        if (NMIX == 3) { float a2 = m2[c]; o2[o + c] = xn * a2 + xx * (1.f - a2); }
        if (t == T_ - 1) shift_out[(long long)b * C_ + c] = xn;
    }
}

// ---------------------------------------------------------------------------
// WKV scan: one thread per (b, channel). Consecutive threads = consecutive
// channels -> fully coalesced loads of k/v/sr each step. Writes sy = sr*y
// and the final (aa, bb, pp) state.
// ---------------------------------------------------------------------------
__global__ __launch_bounds__(256) void wkv_scan_kernel(
    const float* __restrict__ k, const float* __restrict__ v,
    const float* __restrict__ sr,
    const float* __restrict__ td, const float* __restrict__ tf,
    const float* __restrict__ state,
    float* __restrict__ sy, float* __restrict__ out_wkv)
{
    int i = blockIdx.x * blockDim.x + threadIdx.x;  // b*A + a
    int b = i / A_, a = i % A_;
    float w = -expf(td[a]);
    float u = tf[a];
    long long so = ((long long)b * C_ + a) * 3;
    float aa = state[so + 0];
    float bb = state[so + 1];
    float pp = state[so + 2];
    long long o = (long long)b * T_ * A_ + a;
    for (int t = 0; t < T_; t++, o += A_) {
        float kt = k[o], vt = v[o];
        float ww = u + kt;
        float p  = fmaxf(pp, ww);
        float e1 = __expf(pp - p);
        float e2 = __expf(ww - p);
        float y  = (e1 * aa + e2 * vt) / (e1 * bb + e2);
        sy[o] = sr[o] * y;
        float ww2 = pp + w;
        float p2  = fmaxf(ww2, kt);
        e1 = __expf(ww2 - p2);
        e2 = __expf(kt - p2);
        aa = e1 * aa + e2 * vt;
        bb = e1 * bb + e2;
        pp = p2;
    }
    out_wkv[so + 0] = aa;
    out_wkv[so + 1] = bb;
    out_wkv[so + 2] = pp;
}

// ---------------------------------------------------------------------------
// TF32 NT GEMM: out[m,n] = sum_k A[m,k] * B[n,k]; A row-major MxK, B row-major NxK.
// 128x128x32 tile, 256 threads, warp grid 2x4 (warp tile 64x32),
// m16n8k8 tf32 mma.sync, double-buffered smem, fused epilogues.
// All problem dims are multiples of the tile dims (no predication).
// ---------------------------------------------------------------------------
#define GBM 128
#define GBN 128
#define GBK 32
#define GSTR 36                               // 32 + 4 pad floats
#define GEMM_SMEM (4 * GBM * GSTR * 4)        // 2 bufs * (A + B) * 4B = 73728

__device__ __forceinline__ float tf32r(float f) {
    unsigned u;
    asm("cvt.rna.tf32.f32 %0, %1;" : "=r"(u) : "f"(f));
    return __uint_as_float(u);
}

__device__ __forceinline__ void mma8(float c[4], const unsigned a[4], const unsigned b[2]) {
    asm volatile(
        "mma.sync.aligned.m16n8k8.row.col.f32.tf32.tf32.f32 "
        "{%0,%1,%2,%3}, {%4,%5,%6,%7}, {%8,%9}, {%0,%1,%2,%3};"
        : "+f"(c[0]), "+f"(c[1]), "+f"(c[2]), "+f"(c[3])
        : "r"(a[0]), "r"(a[1]), "r"(a[2]), "r"(a[3]), "r"(b[0]), "r"(b[1]));
}

// epilogue modes: 0=store, 1=sigmoid, 2=relu^2, 3=base+acc, 4=base+mul*acc
__device__ __forceinline__ float epi(int mode, float acc,
                                     const float* __restrict__ base,
                                     const float* __restrict__ mul, long long i) {
    switch (mode) {
        case 1:  return 1.f / (1.f + __expf(-acc));
        case 2:  { float t = fmaxf(acc, 0.f); return t * t; }
        case 3:  return base[i] + acc;
        case 4:  return fmaf(mul[i], acc, base[i]);
        default: return acc;
    }
}

__global__ __launch_bounds__(256) void gemm_tf32(
    const float* __restrict__ Ag, const float* __restrict__ Bg,
    float* __restrict__ Og,
    const float* __restrict__ base, const float* __restrict__ mul,
    int M, int N, int K, int mode)
{
    extern __shared__ float sm[];
    float* As = sm;                         // [2][GBM][GSTR]
    float* Bs = sm + 2 * GBM * GSTR;        // [2][GBN][GSTR]

    const int tid  = threadIdx.x;
    const int lane = tid & 31;
    const int warp = tid >> 5;
    const int wm   = (warp & 1) * 64;
    const int wn   = (warp >> 1) * 32;
    const int gid  = lane >> 2;             // 0..7
    const int tig  = lane & 3;              // 0..3
    const long long bm0 = (long long)blockIdx.y * GBM;
    const long long bn0 = (long long)blockIdx.x * GBN;

    float4 ra[4], rb[4];

    auto loadTile = [&](int kt) {
        long long k0 = (long long)kt * GBK;
        #pragma unroll
        for (int i = 0; i < 4; i++) {
            int idx = tid + i * 256;
            int r = idx >> 3, cv = (idx & 7) * 4;
            ra[i] = *(const float4*)(Ag + (bm0 + r) * K + k0 + cv);
            rb[i] = *(const float4*)(Bg + (bn0 + r) * K + k0 + cv);
        }
    };
    auto storeTile = [&](int buf) {
        float* a = As + buf * GBM * GSTR;
        float* b = Bs + buf * GBN * GSTR;
        #pragma unroll
        for (int i = 0; i < 4; i++) {
            int idx = tid + i * 256;
            int r = idx >> 3, cv = (idx & 7) * 4;
            float4 ta = ra[i], tb = rb[i];
            ta.x = tf32r(ta.x); ta.y = tf32r(ta.y); ta.z = tf32r(ta.z); ta.w = tf32r(ta.w);
            tb.x = tf32r(tb.x); tb.y = tf32r(tb.y); tb.z = tf32r(tb.z); tb.w = tf32r(tb.w);
            *(float4*)(a + r * GSTR + cv) = ta;
            *(float4*)(b + r * GSTR + cv) = tb;
        }
    };

    float acc[4][4][4];
    #pragma unroll
    for (int mi = 0; mi < 4; mi++)
        #pragma unroll
        for (int ni = 0; ni < 4; ni++)
            #pragma unroll
            for (int q = 0; q < 4; q++) acc[mi][ni][q] = 0.f;

    loadTile(0);
    storeTile(0);
    __syncthreads();

    const int nk = K / GBK;
    for (int kt = 0; kt < nk; kt++) {
        int buf = kt & 1;
        if (kt + 1 < nk) loadTile(kt + 1);
        const float* a = As + buf * GBM * GSTR;
        const float* b = Bs + buf * GBN * GSTR;
        #pragma unroll
        for (int ks = 0; ks < 4; ks++) {
            unsigned af[4][4], bf[4][2];
            #pragma unroll
            for (int mi = 0; mi < 4; mi++) {
                const float* p = a + (wm + mi * 16 + gid) * GSTR + ks * 8 + tig;
                af[mi][0] = __float_as_uint(p[0]);
                af[mi][1] = __float_as_uint(p[8 * GSTR]);
                af[mi][2] = __float_as_uint(p[4]);
                af[mi][3] = __float_as_uint(p[8 * GSTR + 4]);
            }
            #pragma unroll
            for (int ni = 0; ni < 4; ni++) {
                const float* p = b + (wn + ni * 8 + gid) * GSTR + ks * 8 + tig;
                bf[ni][0] = __float_as_uint(p[0]);
                bf[ni][1] = __float_as_uint(p[4]);
            }
            #pragma unroll
            for (int mi = 0; mi < 4; mi++)
                #pragma unroll
                for (int ni = 0; ni < 4; ni++)
                    mma8(acc[mi][ni], af[mi], bf[ni]);
        }
        if (kt + 1 < nk) {
            storeTile((kt + 1) & 1);
            __syncthreads();
        }
    }

    // epilogue
    #pragma unroll
    for (int mi = 0; mi < 4; mi++) {
        #pragma unroll
        for (int ni = 0; ni < 4; ni++) {
            long long row = bm0 + wm + mi * 16 + gid;
            long long col = bn0 + wn + ni * 8 + 2 * tig;
            long long i0 = row * N + col;
            long long i1 = (row + 8) * N + col;
            Og[i0]     = epi(mode, acc[mi][ni][0], base, mul, i0);
            Og[i0 + 1] = epi(mode, acc[mi][ni][1], base, mul, i0 + 1);
            Og[i1]     = epi(mode, acc[mi][ni][2], base, mul, i1);
            Og[i1 + 1] = epi(mode, acc[mi][ni][3], base, mul, i1 + 1);
        }
    }
}

// ---------------------------------------------------------------------------
// Launcher
// ---------------------------------------------------------------------------
extern "C" void kernel_launch(void* const* d_in, const int* in_sizes, int n_in,
                              void* d_out, int out_size)
{
    const float* x    = (const float*)d_in[0];
    const float* tm   = (const float*)d_in[1];
    const float* st   = (const float*)d_in[2];
    const float* cm   = (const float*)d_in[3];
    const float* g1   = (const float*)d_in[4];
    const float* b1   = (const float*)d_in[5];
    const float* g2   = (const float*)d_in[6];
    const float* b2   = (const float*)d_in[7];
    const float* td   = (const float*)d_in[8];
    const float* tfst = (const float*)d_in[9];
    const float* amk  = (const float*)d_in[10];
    const float* amv  = (const float*)d_in[11];
    const float* amr  = (const float*)d_in[12];
    const float* Wk   = (const float*)d_in[13];
    const float* Wv   = (const float*)d_in[14];
    const float* Wr   = (const float*)d_in[15];
    const float* Wo   = (const float*)d_in[16];
    const float* fmk  = (const float*)d_in[17];
    const float* fmr  = (const float*)d_in[18];
    const float* Wkf  = (const float*)d_in[19];
    const float* Wrf  = (const float*)d_in[20];
    const float* Wvf  = (const float*)d_in[21];

    float* out     = (float*)d_out;
    float* out_x   = out;
    float* out_wkv = out + BTCll;
    float* out_tm  = out_wkv + (long long)B_ * C_ * 3;
    float* out_cm  = out_tm + (long long)B_ * C_;

    float* buf = nullptr;
    cudaGetSymbolAddress((void**)&buf, g_buf);
    float* xk = buf + 0 * BTCll;
    float* xv = buf + 1 * BTCll;
    float* xr = buf + 2 * BTCll;
    float* kk = buf + 3 * BTCll;
    float* vv = buf + 4 * BTCll;
    float* sr = buf + 5 * BTCll;
    float* sy = buf + 6 * BTCll;
    float* kf = buf + 7 * BTCll;

    cudaFuncSetAttribute((const void*)gemm_tf32,
                         cudaFuncAttributeMaxDynamicSharedMemorySize, GEMM_SMEM);

    const int M = B_ * T_;

    // --- attention path ---
    ln_mix_kernel<3><<<M, 256>>>(x, tm, g1, b1, amk, amv, amr, xk, xv, xr, out_tm);

    gemm_tf32<<<dim3(A_ / GBN, M / GBM), 256, GEMM_SMEM>>>(xk, Wk, kk, nullptr, nullptr, M, A_, C_, 0);
    gemm_tf32<<<dim3(A_ / GBN, M / GBM), 256, GEMM_SMEM>>>(xv, Wv, vv, nullptr, nullptr, M, A_, C_, 0);
    gemm_tf32<<<dim3(A_ / GBN, M / GBM), 256, GEMM_SMEM>>>(xr, Wr, sr, nullptr, nullptr, M, A_, C_, 1);

    wkv_scan_kernel<<<(B_ * A_) / 256, 256>>>(kk, vv, sr, td, tfst, st, sy, out_wkv);

    gemm_tf32<<<dim3(C_ / GBN, M / GBM), 256, GEMM_SMEM>>>(sy, Wo, out_x, x, nullptr, M, C_, A_, 3);

    // --- ffn path ---
    ln_mix_kernel<2><<<M, 256>>>(out_x, cm, g2, b2, fmk, fmr, nullptr, xk, xr, nullptr, out_cm);

    gemm_tf32<<<dim3(FF_ / GBN, M / GBM), 256, GEMM_SMEM>>>(xk, Wkf, kf, nullptr, nullptr, M, FF_, C_, 2);
    gemm_tf32<<<dim3(C_ / GBN, M / GBM), 256, GEMM_SMEM>>>(xr, Wrf, vv, nullptr, nullptr, M, C_, C_, 1);
    gemm_tf32<<<dim3(C_ / GBN, M / GBM), 256, GEMM_SMEM>>>(kf, Wvf, out_x, out_x, vv, M, C_, FF_, 4);
}

// round 3
// speedup vs baseline: 1.1896x; 1.1896x over previous
#include <cuda_runtime.h>
#include <cstdint>
#include <math.h>

// ---------------------------------------------------------------------------
// RWKV-v4 block: B=4, T=4096, C=2048, A=2048, FF=8192
// mma.sync tf32 GEMMs (tcgen05 unavailable: harness PTX target is plain
// sm_103, no 'a' feature set), cp.async 3-stage pipeline, 64x64 warp tiles.
// All GEMM inputs pre-rounded to tf32-rna at their producers so raw cp.async
// copies + HW truncation are numerically exact.
// ---------------------------------------------------------------------------

#define B_  4
#define T_  4096
#define C_  2048
#define A_  2048
#define FF_ 8192

#define BTCll ((long long)B_ * T_ * C_)   // 33,554,432
#define BTFll ((long long)B_ * T_ * FF_)  // 134,217,728
#define ACll  ((long long)A_ * C_)        // 4,194,304
#define FCll  ((long long)FF_ * C_)       // 16,777,216

// Scratch: xk,xv,xr,k,v,sr,sy (7*BTC) + kf (BTF) + rounded weights (54.5M)
__device__ float g_buf[7LL * 33554432LL + 134217728LL + 54525952LL];

// ---------------------------------------------------------------------------
// helpers
// ---------------------------------------------------------------------------
__device__ __forceinline__ float tf32r(float f) {
    unsigned u;
    asm("cvt.rna.tf32.f32 %0, %1;" : "=r"(u) : "f"(f));
    return __uint_as_float(u);
}

__device__ __forceinline__ uint32_t s2u(const void* p) {
    return (uint32_t)__cvta_generic_to_shared(p);
}

__device__ __forceinline__ void cpa16(uint32_t dst, const void* src) {
    asm volatile("cp.async.cg.shared.global [%0], [%1], 16;" :: "r"(dst), "l"(src));
}

__device__ __forceinline__ void mma8(float c[4], const unsigned a[4], const unsigned b[2]) {
    asm volatile(
        "mma.sync.aligned.m16n8k8.row.col.f32.tf32.tf32.f32 "
        "{%0,%1,%2,%3}, {%4,%5,%6,%7}, {%8,%9}, {%0,%1,%2,%3};"
        : "+f"(c[0]), "+f"(c[1]), "+f"(c[2]), "+f"(c[3])
        : "r"(a[0]), "r"(a[1]), "r"(a[2]), "r"(a[3]), "r"(b[0]), "r"(b[1]));
}

// ---------------------------------------------------------------------------
// Weight pre-rounding to tf32
// ---------------------------------------------------------------------------
__global__ __launch_bounds__(256) void round_tf32_kernel(
    const float* __restrict__ s, float* __restrict__ d, int n4)
{
    int i = blockIdx.x * blockDim.x + threadIdx.x;
    if (i >= n4) return;
    float4 v = ((const float4*)s)[i];
    v.x = tf32r(v.x); v.y = tf32r(v.y); v.z = tf32r(v.z); v.w = tf32r(v.w);
    ((float4*)d)[i] = v;
}

// ---------------------------------------------------------------------------
// Block reduce of 4 values (256 threads)
// ---------------------------------------------------------------------------
__device__ __forceinline__ void blockReduce4(float& a, float& b, float& c, float& d) {
    #pragma unroll
    for (int o = 16; o > 0; o >>= 1) {
        a += __shfl_down_sync(0xffffffffu, a, o);
        b += __shfl_down_sync(0xffffffffu, b, o);
        c += __shfl_down_sync(0xffffffffu, c, o);
        d += __shfl_down_sync(0xffffffffu, d, o);
    }
    __shared__ float sh[8][4];
    int w = threadIdx.x >> 5, l = threadIdx.x & 31;
    if (l == 0) { sh[w][0] = a; sh[w][1] = b; sh[w][2] = c; sh[w][3] = d; }
    __syncthreads();
    if (threadIdx.x == 0) {
        float ta = 0, tb = 0, tc = 0, td = 0;
        #pragma unroll
        for (int i = 0; i < 8; i++) { ta += sh[i][0]; tb += sh[i][1]; tc += sh[i][2]; td += sh[i][3]; }
        sh[0][0] = ta; sh[0][1] = tb; sh[0][2] = tc; sh[0][3] = td;
    }
    __syncthreads();
    a = sh[0][0]; b = sh[0][1]; c = sh[0][2]; d = sh[0][3];
}

// ---------------------------------------------------------------------------
// LayerNorm + shift mix (outputs rounded to tf32; they only feed GEMM A-ops)
// ---------------------------------------------------------------------------
template <int NMIX>
__global__ __launch_bounds__(256) void ln_mix_kernel(
    const float* __restrict__ x, const float* __restrict__ shift_in,
    const float* __restrict__ gw, const float* __restrict__ bw,
    const float* __restrict__ m0, const float* __restrict__ m1, const float* __restrict__ m2,
    float* __restrict__ o0, float* __restrict__ o1, float* __restrict__ o2,
    float* __restrict__ shift_out)
{
    const int bt = blockIdx.x;
    const int b = bt / T_, t = bt % T_;
    const int tid = threadIdx.x;
    const float* xr = x + (long long)bt * C_;

    float cur[8], prv[8];
    float s1 = 0.f, s2 = 0.f, p1 = 0.f, p2 = 0.f;
    #pragma unroll
    for (int i = 0; i < 8; i++) {
        int c = tid + i * 256;
        float v = xr[c];
        cur[i] = v; s1 += v; s2 += v * v;
        if (t > 0) {
            float w = xr[c - C_];
            prv[i] = w; p1 += w; p2 += w * w;
        } else prv[i] = 0.f;
    }
    blockReduce4(s1, s2, p1, p2);
    const float inv = 1.f / (float)C_;
    float mu = s1 * inv;
    float rs = rsqrtf(s2 * inv - mu * mu + 1e-5f);
    float mup = 0.f, rsp = 0.f;
    if (t > 0) {
        mup = p1 * inv;
        rsp = rsqrtf(p2 * inv - mup * mup + 1e-5f);
    }
    long long o = (long long)bt * C_;
    #pragma unroll
    for (int i = 0; i < 8; i++) {
        int c = tid + i * 256;
        float gg = gw[c], bb = bw[c];
        float xn = (cur[i] - mu) * rs * gg + bb;
        float xx = (t > 0) ? ((prv[i] - mup) * rsp * gg + bb)
                           : shift_in[(long long)b * C_ + c];
        float a0 = m0[c]; o0[o + c] = tf32r(xn * a0 + xx * (1.f - a0));
        float a1 = m1[c]; o1[o + c] = tf32r(xn * a1 + xx * (1.f - a1));
        if (NMIX == 3) { float a2 = m2[c]; o2[o + c] = tf32r(xn * a2 + xx * (1.f - a2)); }
        if (t == T_ - 1) shift_out[(long long)b * C_ + c] = xn;
    }
}

// ---------------------------------------------------------------------------
// WKV scan: one thread per (b,channel), 64-thread blocks
// ---------------------------------------------------------------------------
__global__ __launch_bounds__(64) void wkv_scan_kernel(
    const float* __restrict__ k, const float* __restrict__ v,
    const float* __restrict__ sr,
    const float* __restrict__ td, const float* __restrict__ tf,
    const float* __restrict__ state,
    float* __restrict__ sy, float* __restrict__ out_wkv)
{
    int i = blockIdx.x * blockDim.x + threadIdx.x;  // b*A + a
    int b = i / A_, a = i % A_;
    float w = -expf(td[a]);
    float u = tf[a];
    long long so = ((long long)b * C_ + a) * 3;
    float aa = state[so + 0];
    float bb = state[so + 1];
    float pp = state[so + 2];
    long long o = (long long)b * T_ * A_ + a;
    float kt = k[o], vt = v[o], rt = sr[o];
    for (int t = 0; t < T_; t++) {
        long long on = o + A_;
        float kn = 0.f, vn = 0.f, rn = 0.f;
        if (t + 1 < T_) { kn = k[on]; vn = v[on]; rn = sr[on]; }
        float ww = u + kt;
        float p  = fmaxf(pp, ww);
        float e1 = __expf(pp - p);
        float e2 = __expf(ww - p);
        float y  = __fdividef(e1 * aa + e2 * vt, e1 * bb + e2);
        sy[o] = tf32r(rt * y);
        float ww2 = pp + w;
        float p2  = fmaxf(ww2, kt);
        e1 = __expf(ww2 - p2);
        e2 = __expf(kt - p2);
        aa = e1 * aa + e2 * vt;
        bb = e1 * bb + e2;
        pp = p2;
        o = on; kt = kn; vt = vn; rt = rn;
    }
    out_wkv[so + 0] = aa;
    out_wkv[so + 1] = bb;
    out_wkv[so + 2] = pp;
}

// ---------------------------------------------------------------------------
// TF32 NT GEMM via mma.sync: out[m,n] = sum_k A[m,k]*B[n,k]
// CTA 128x128x32, 128 threads (4 warps, warp tile 64x64), cp.async 3-stage.
// Epilogue modes: 0=store, 1=sigmoid, 2=tf32(relu^2), 3=base+acc, 4=base+mul*acc
// ---------------------------------------------------------------------------
#define GBK  32
#define GSTR 36
#define STG_FLOATS (2 * 128 * GSTR)            // A+B per stage = 9216 floats
#define NSTG 3
#define GEMM_SMEM (NSTG * STG_FLOATS * 4)      // 110592 B -> 2 CTAs/SM

__device__ __forceinline__ float epi(int mode, float acc,
                                     const float* __restrict__ base,
                                     const float* __restrict__ mul, long long i) {
    switch (mode) {
        case 1:  return 1.f / (1.f + __expf(-acc));
        case 2:  { float t = fmaxf(acc, 0.f); return tf32r(t * t); }
        case 3:  return base[i] + acc;
        case 4:  return fmaf(mul[i], acc, base[i]);
        default: return acc;
    }
}

__global__ __launch_bounds__(128, 2) void gemm_tf32(
    const float* __restrict__ Ag, const float* __restrict__ Bg,
    float* __restrict__ Og,
    const float* __restrict__ base, const float* __restrict__ mul,
    int M, int N, int K, int mode, int tiles_n)
{
    extern __shared__ float sm[];

    const int tid  = threadIdx.x;
    const int lane = tid & 31;
    const int warp = tid >> 5;            // 0..3
    const int wm   = (warp & 1) * 64;
    const int wn   = (warp >> 1) * 64;
    const int gid  = lane >> 2;           // 0..7
    const int tig  = lane & 3;            // 0..3

    // rasterization: groups of 16 M-tiles; consecutive blocks share B tile
    const int per = 16 * tiles_n;
    const int grp = blockIdx.x / per, rem = blockIdx.x % per;
    const int mt = grp * 16 + (rem % 16);
    const int nt = rem / 16;
    const long long bm0 = (long long)mt * 128, bn0 = (long long)nt * 128;

    // per-thread cp.async source/dest precompute
    const int ldr = tid >> 3;             // 0..15 base row
    const int ldc = (tid & 7) * 4;        // float col {0,4,...,28}

    auto load_stage = [&](int j) {
        float* As = sm + (j % NSTG) * STG_FLOATS;
        float* Bs = As + 128 * GSTR;
        const long long k0 = (long long)j * GBK;
        const float* Ap = Ag + (bm0 + ldr) * K + k0 + ldc;
        const float* Bp = Bg + (bn0 + ldr) * K + k0 + ldc;
        uint32_t da = s2u(As + ldr * GSTR + ldc);
        uint32_t db = s2u(Bs + ldr * GSTR + ldc);
        #pragma unroll
        for (int i = 0; i < 8; i++) {
            cpa16(da + i * 16 * GSTR * 4, Ap + (long long)i * 16 * K);
            cpa16(db + i * 16 * GSTR * 4, Bp + (long long)i * 16 * K);
        }
    };

    float acc[4][8][4];
    #pragma unroll
    for (int mi = 0; mi < 4; mi++)
        #pragma unroll
        for (int ni = 0; ni < 8; ni++)
            #pragma unroll
            for (int q = 0; q < 4; q++) acc[mi][ni][q] = 0.f;

    const int nk = K >> 5;
    load_stage(0);
    asm volatile("cp.async.commit_group;" ::: "memory");
    load_stage(1);
    asm volatile("cp.async.commit_group;" ::: "memory");

    for (int j = 0; j < nk; j++) {
        asm volatile("cp.async.wait_group 1;" ::: "memory");
        __syncthreads();
        if (j + 2 < nk) load_stage(j + 2);
        asm volatile("cp.async.commit_group;" ::: "memory");

        const float* a = sm + (j % NSTG) * STG_FLOATS;
        const float* b = a + 128 * GSTR;
        #pragma unroll
        for (int ks = 0; ks < 4; ks++) {
            unsigned af[4][4], bf[8][2];
            #pragma unroll
            for (int mi = 0; mi < 4; mi++) {
                const float* p = a + (wm + mi * 16 + gid) * GSTR + ks * 8 + tig;
                af[mi][0] = __float_as_uint(p[0]);
                af[mi][1] = __float_as_uint(p[8 * GSTR]);
                af[mi][2] = __float_as_uint(p[4]);
                af[mi][3] = __float_as_uint(p[8 * GSTR + 4]);
            }
            #pragma unroll
            for (int ni = 0; ni < 8; ni++) {
                const float* p = b + (wn + ni * 8 + gid) * GSTR + ks * 8 + tig;
                bf[ni][0] = __float_as_uint(p[0]);
                bf[ni][1] = __float_as_uint(p[4]);
            }
            #pragma unroll
            for (int mi = 0; mi < 4; mi++)
                #pragma unroll
                for (int ni = 0; ni < 8; ni++)
                    mma8(acc[mi][ni], af[mi], bf[ni]);
        }
        __syncthreads();
    }

    // epilogue: direct stores, 8B vectors, sector-aligned per quad
    #pragma unroll
    for (int mi = 0; mi < 4; mi++) {
        #pragma unroll
        for (int ni = 0; ni < 8; ni++) {
            long long row = bm0 + wm + mi * 16 + gid;
            long long col = bn0 + wn + ni * 8 + 2 * tig;
            long long i0 = row * N + col;
            long long i1 = (row + 8) * N + col;
            float2 v0, v1;
            v0.x = epi(mode, acc[mi][ni][0], base, mul, i0);
            v0.y = epi(mode, acc[mi][ni][1], base, mul, i0 + 1);
            v1.x = epi(mode, acc[mi][ni][2], base, mul, i1);
            v1.y = epi(mode, acc[mi][ni][3], base, mul, i1 + 1);
            *(float2*)(Og + i0) = v0;
            *(float2*)(Og + i1) = v1;
        }
    }
}

// ---------------------------------------------------------------------------
// Launcher
// ---------------------------------------------------------------------------
extern "C" void kernel_launch(void* const* d_in, const int* in_sizes, int n_in,
                              void* d_out, int out_size)
{
    const float* x    = (const float*)d_in[0];
    const float* tm   = (const float*)d_in[1];
    const float* st   = (const float*)d_in[2];
    const float* cm   = (const float*)d_in[3];
    const float* g1   = (const float*)d_in[4];
    const float* b1   = (const float*)d_in[5];
    const float* g2   = (const float*)d_in[6];
    const float* b2   = (const float*)d_in[7];
    const float* td   = (const float*)d_in[8];
    const float* tfst = (const float*)d_in[9];
    const float* amk  = (const float*)d_in[10];
    const float* amv  = (const float*)d_in[11];
    const float* amr  = (const float*)d_in[12];
    const float* Wk   = (const float*)d_in[13];
    const float* Wv   = (const float*)d_in[14];
    const float* Wr   = (const float*)d_in[15];
    const float* Wo   = (const float*)d_in[16];
    const float* fmk  = (const float*)d_in[17];
    const float* fmr  = (const float*)d_in[18];
    const float* Wkf  = (const float*)d_in[19];
    const float* Wrf  = (const float*)d_in[20];
    const float* Wvf  = (const float*)d_in[21];

    float* out     = (float*)d_out;
    float* out_x   = out;
    float* out_wkv = out + BTCll;
    float* out_tm  = out_wkv + (long long)B_ * C_ * 3;
    float* out_cm  = out_tm + (long long)B_ * C_;

    float* buf = nullptr;
    cudaGetSymbolAddress((void**)&buf, g_buf);
    float* xk = buf + 0 * BTCll;
    float* xv = buf + 1 * BTCll;
    float* xr = buf + 2 * BTCll;
    float* kk = buf + 3 * BTCll;
    float* vv = buf + 4 * BTCll;
    float* sr = buf + 5 * BTCll;
    float* sy = buf + 6 * BTCll;
    float* kf = buf + 7 * BTCll;
    float* w  = kf + BTFll;
    float* rWk  = w;               // A*C
    float* rWv  = rWk + ACll;
    float* rWr  = rWv + ACll;
    float* rWo  = rWr + ACll;
    float* rWkf = rWo + ACll;      // FF*C
    float* rWrf = rWkf + FCll;     // C*C
    float* rWvf = rWrf + ACll;     // C*FF

    cudaFuncSetAttribute((const void*)gemm_tf32,
                         cudaFuncAttributeMaxDynamicSharedMemorySize, GEMM_SMEM);

    const int M = B_ * T_;
    const int tm_ = M / 128;

    // weight pre-rounding (tf32-rna; makes HW truncation exact)
    round_tf32_kernel<<<(int)(ACll / 4 / 256), 256>>>(Wk,  rWk,  (int)(ACll / 4));
    round_tf32_kernel<<<(int)(ACll / 4 / 256), 256>>>(Wv,  rWv,  (int)(ACll / 4));
    round_tf32_kernel<<<(int)(ACll / 4 / 256), 256>>>(Wr,  rWr,  (int)(ACll / 4));
    round_tf32_kernel<<<(int)(ACll / 4 / 256), 256>>>(Wo,  rWo,  (int)(ACll / 4));
    round_tf32_kernel<<<(int)(FCll / 4 / 256), 256>>>(Wkf, rWkf, (int)(FCll / 4));
    round_tf32_kernel<<<(int)(ACll / 4 / 256), 256>>>(Wrf, rWrf, (int)(ACll / 4));
    round_tf32_kernel<<<(int)(FCll / 4 / 256), 256>>>(Wvf, rWvf, (int)(FCll / 4));

    // --- attention path ---
    ln_mix_kernel<3><<<M, 256>>>(x, tm, g1, b1, amk, amv, amr, xk, xv, xr, out_tm);

    gemm_tf32<<<tm_ * (A_ / 128), 128, GEMM_SMEM>>>(xk, rWk, kk, nullptr, nullptr, M, A_, C_, 0, A_ / 128);
    gemm_tf32<<<tm_ * (A_ / 128), 128, GEMM_SMEM>>>(xv, rWv, vv, nullptr, nullptr, M, A_, C_, 0, A_ / 128);
    gemm_tf32<<<tm_ * (A_ / 128), 128, GEMM_SMEM>>>(xr, rWr, sr, nullptr, nullptr, M, A_, C_, 1, A_ / 128);

    wkv_scan_kernel<<<(B_ * A_) / 64, 64>>>(kk, vv, sr, td, tfst, st, sy, out_wkv);

    gemm_tf32<<<tm_ * (C_ / 128), 128, GEMM_SMEM>>>(sy, rWo, out_x, x, nullptr, M, C_, A_, 3, C_ / 128);

    // --- ffn path ---
    ln_mix_kernel<2><<<M, 256>>>(out_x, cm, g2, b2, fmk, fmr, nullptr, xk, xr, nullptr, out_cm);

    gemm_tf32<<<tm_ * (FF_ / 128), 128, GEMM_SMEM>>>(xk, rWkf, kf, nullptr, nullptr, M, FF_, C_, 2, FF_ / 128);
    gemm_tf32<<<tm_ * (C_ / 128), 128, GEMM_SMEM>>>(xr, rWrf, vv, nullptr, nullptr, M, C_, C_, 1, C_ / 128);
    gemm_tf32<<<tm_ * (C_ / 128), 128, GEMM_SMEM>>>(kf, rWvf, out_x, out_x, vv, M, C_, FF_, 4, C_ / 128);
}

// round 4
// speedup vs baseline: 2.0545x; 1.7271x over previous
#include <cuda_runtime.h>
#include <cuda_fp16.h>
#include <cstdint>
#include <math.h>

// ---------------------------------------------------------------------------
// RWKV-v4 block: B=4, T=4096, C=2048, A=2048, FF=8192
// fp16 mma.sync (m16n8k16) GEMMs with fp32 accumulate. fp16 mantissa == tf32
// mantissa (10 bits), so precision matches the passing tf32 version, at 2x
// the legacy-HMMA pipe rate. All GEMM inputs converted to fp16 at producers.
// ---------------------------------------------------------------------------

#define B_  4
#define T_  4096
#define C_  2048
#define A_  2048
#define FF_ 8192

#define BTCll ((long long)B_ * T_ * C_)   // 33,554,432
#define BTFll ((long long)B_ * T_ * FF_)  // 134,217,728
#define ACll  ((long long)A_ * C_)        // 4,194,304
#define FCll  ((long long)FF_ * C_)       // 16,777,216

// float-unit layout:
// xk_h,xv_h,xr_h (BTC/2 each) | kk,vv,sr (BTC each) | sy_h (BTC/2)
// | kf_h (BTF/2) | hW (all fp16 weights, (5AC+2FC)/2)
__device__ float g_buf[262144000LL];

// ---------------------------------------------------------------------------
// helpers
// ---------------------------------------------------------------------------
__device__ __forceinline__ uint32_t s2u(const void* p) {
    return (uint32_t)__cvta_generic_to_shared(p);
}

__device__ __forceinline__ void cpa16(uint32_t dst, const void* src) {
    asm volatile("cp.async.cg.shared.global [%0], [%1], 16;" :: "r"(dst), "l"(src));
}

__device__ __forceinline__ void mma16(float c[4], const unsigned a[4], const unsigned b[2]) {
    asm volatile(
        "mma.sync.aligned.m16n8k16.row.col.f32.f16.f16.f32 "
        "{%0,%1,%2,%3}, {%4,%5,%6,%7}, {%8,%9}, {%0,%1,%2,%3};"
        : "+f"(c[0]), "+f"(c[1]), "+f"(c[2]), "+f"(c[3])
        : "r"(a[0]), "r"(a[1]), "r"(a[2]), "r"(a[3]), "r"(b[0]), "r"(b[1]));
}

// ---------------------------------------------------------------------------
// Weight conversion fp32 -> fp16 (fused: 2 launches total)
// ---------------------------------------------------------------------------
__global__ __launch_bounds__(256) void conv_att_kernel(
    const float* __restrict__ w0, const float* __restrict__ w1,
    const float* __restrict__ w2, const float* __restrict__ w3,
    __half* __restrict__ d)  // 4 segments of AC floats each
{
    long long i4 = (long long)blockIdx.x * 256 + threadIdx.x;   // float4 index
    const long long segq = ACll / 4;
    int seg = (int)(i4 / segq);
    long long loc = (i4 - (long long)seg * segq) * 4;
    const float* s = (seg == 0) ? w0 : (seg == 1) ? w1 : (seg == 2) ? w2 : w3;
    float4 v = *(const float4*)(s + loc);
    __half2* o = (__half2*)(d + (long long)seg * ACll + loc);
    o[0] = __floats2half2_rn(v.x, v.y);
    o[1] = __floats2half2_rn(v.z, v.w);
}

__global__ __launch_bounds__(256) void conv_ffn_kernel(
    const float* __restrict__ wkf, const float* __restrict__ wrf,
    const float* __restrict__ wvf, __half* __restrict__ d)  // FC, AC, FC
{
    long long i4 = (long long)blockIdx.x * 256 + threadIdx.x;
    const long long q0 = FCll / 4, q1 = q0 + ACll / 4;
    const float* s;
    long long loc, dof;
    if (i4 < q0)      { s = wkf; loc = i4 * 4;        dof = loc; }
    else if (i4 < q1) { s = wrf; loc = (i4 - q0) * 4; dof = FCll + loc; }
    else              { s = wvf; loc = (i4 - q1) * 4; dof = FCll + ACll + loc; }
    float4 v = *(const float4*)(s + loc);
    __half2* o = (__half2*)(d + dof);
    o[0] = __floats2half2_rn(v.x, v.y);
    o[1] = __floats2half2_rn(v.z, v.w);
}

// ---------------------------------------------------------------------------
// Block reduce of 4 values (256 threads)
// ---------------------------------------------------------------------------
__device__ __forceinline__ void blockReduce4(float& a, float& b, float& c, float& d) {
    #pragma unroll
    for (int o = 16; o > 0; o >>= 1) {
        a += __shfl_down_sync(0xffffffffu, a, o);
        b += __shfl_down_sync(0xffffffffu, b, o);
        c += __shfl_down_sync(0xffffffffu, c, o);
        d += __shfl_down_sync(0xffffffffu, d, o);
    }
    __shared__ float sh[8][4];
    int w = threadIdx.x >> 5, l = threadIdx.x & 31;
    if (l == 0) { sh[w][0] = a; sh[w][1] = b; sh[w][2] = c; sh[w][3] = d; }
    __syncthreads();
    if (threadIdx.x == 0) {
        float ta = 0, tb = 0, tc = 0, td = 0;
        #pragma unroll
        for (int i = 0; i < 8; i++) { ta += sh[i][0]; tb += sh[i][1]; tc += sh[i][2]; td += sh[i][3]; }
        sh[0][0] = ta; sh[0][1] = tb; sh[0][2] = tc; sh[0][3] = td;
    }
    __syncthreads();
    a = sh[0][0]; b = sh[0][1]; c = sh[0][2]; d = sh[0][3];
}

// ---------------------------------------------------------------------------
// LayerNorm + shift mix -> fp16 outputs (GEMM A operands)
// ---------------------------------------------------------------------------
template <int NMIX>
__global__ __launch_bounds__(256) void ln_mix_kernel(
    const float* __restrict__ x, const float* __restrict__ shift_in,
    const float* __restrict__ gw, const float* __restrict__ bw,
    const float* __restrict__ m0, const float* __restrict__ m1, const float* __restrict__ m2,
    __half* __restrict__ o0, __half* __restrict__ o1, __half* __restrict__ o2,
    float* __restrict__ shift_out)
{
    const int bt = blockIdx.x;
    const int b = bt / T_, t = bt % T_;
    const int tid = threadIdx.x;
    const float* xr = x + (long long)bt * C_;

    float cur[8], prv[8];
    float s1 = 0.f, s2 = 0.f, p1 = 0.f, p2 = 0.f;
    #pragma unroll
    for (int i = 0; i < 8; i++) {
        int c = tid + i * 256;
        float v = xr[c];
        cur[i] = v; s1 += v; s2 += v * v;
        if (t > 0) {
            float w = xr[c - C_];
            prv[i] = w; p1 += w; p2 += w * w;
        } else prv[i] = 0.f;
    }
    blockReduce4(s1, s2, p1, p2);
    const float inv = 1.f / (float)C_;
    float mu = s1 * inv;
    float rs = rsqrtf(s2 * inv - mu * mu + 1e-5f);
    float mup = 0.f, rsp = 0.f;
    if (t > 0) {
        mup = p1 * inv;
        rsp = rsqrtf(p2 * inv - mup * mup + 1e-5f);
    }
    long long o = (long long)bt * C_;
    #pragma unroll
    for (int i = 0; i < 8; i++) {
        int c = tid + i * 256;
        float gg = gw[c], bb = bw[c];
        float xn = (cur[i] - mu) * rs * gg + bb;
        float xx = (t > 0) ? ((prv[i] - mup) * rsp * gg + bb)
                           : shift_in[(long long)b * C_ + c];
        float a0 = m0[c]; o0[o + c] = __float2half_rn(xn * a0 + xx * (1.f - a0));
        float a1 = m1[c]; o1[o + c] = __float2half_rn(xn * a1 + xx * (1.f - a1));
        if (NMIX == 3) { float a2 = m2[c]; o2[o + c] = __float2half_rn(xn * a2 + xx * (1.f - a2)); }
        if (t == T_ - 1) shift_out[(long long)b * C_ + c] = xn;
    }
}

// ---------------------------------------------------------------------------
// WKV scan: one thread per (b,channel); sy emitted as fp16 for the Wo GEMM
// ---------------------------------------------------------------------------
__global__ __launch_bounds__(64) void wkv_scan_kernel(
    const float* __restrict__ k, const float* __restrict__ v,
    const float* __restrict__ sr,
    const float* __restrict__ td, const float* __restrict__ tf,
    const float* __restrict__ state,
    __half* __restrict__ sy, float* __restrict__ out_wkv)
{
    int i = blockIdx.x * blockDim.x + threadIdx.x;  // b*A + a
    int b = i / A_, a = i % A_;
    float w = -expf(td[a]);
    float u = tf[a];
    long long so = ((long long)b * C_ + a) * 3;
    float aa = state[so + 0];
    float bb = state[so + 1];
    float pp = state[so + 2];
    long long o = (long long)b * T_ * A_ + a;
    float kt = k[o], vt = v[o], rt = sr[o];
    for (int t = 0; t < T_; t++) {
        long long on = o + A_;
        float kn = 0.f, vn = 0.f, rn = 0.f;
        if (t + 1 < T_) { kn = k[on]; vn = v[on]; rn = sr[on]; }
        float ww = u + kt;
        float p  = fmaxf(pp, ww);
        float e1 = __expf(pp - p);
        float e2 = __expf(ww - p);
        float y  = __fdividef(e1 * aa + e2 * vt, e1 * bb + e2);
        sy[o] = __float2half_rn(rt * y);
        float ww2 = pp + w;
        float p2  = fmaxf(ww2, kt);
        e1 = __expf(ww2 - p2);
        e2 = __expf(kt - p2);
        aa = e1 * aa + e2 * vt;
        bb = e1 * bb + e2;
        pp = p2;
        o = on; kt = kn; vt = vn; rt = rn;
    }
    out_wkv[so + 0] = aa;
    out_wkv[so + 1] = bb;
    out_wkv[so + 2] = pp;
}

// ---------------------------------------------------------------------------
// FP16 NT GEMM via mma.sync m16n8k16: out[m,n] = sum_k A[m,k]*B[n,k]
// CTA 128x128x64, 128 threads (4 warps, warp tile 64x64), cp.async 3-stage.
// MODE: 0=store f32, 1=sigmoid f32, 2=relu^2 -> fp16, 3=base+acc, 4=base+mul*acc
// ---------------------------------------------------------------------------
#define GBK   64
#define HSTR  72                               // halfs per smem row (64+8 pad)
#define STG_H (2 * 128 * HSTR)                 // A+B rows per stage, in halfs
#define NSTG  3
#define GEMM_SMEM (NSTG * STG_H * 2)           // 110592 B -> 2 CTAs/SM

template <int MODE>
__global__ __launch_bounds__(128, 2) void gemm_h(
    const __half* __restrict__ Ag, const __half* __restrict__ Bg,
    void* __restrict__ Ogv,
    const float* __restrict__ base, const float* __restrict__ mul,
    int M, int N, int K, int tiles_n)
{
    extern __shared__ __half sm[];

    const int tid  = threadIdx.x;
    const int lane = tid & 31;
    const int warp = tid >> 5;            // 0..3
    const int wm   = (warp & 1) * 64;
    const int wn   = (warp >> 1) * 64;
    const int gid  = lane >> 2;           // 0..7
    const int tig  = lane & 3;            // 0..3

    // rasterization: groups of 16 M-tiles; consecutive blocks share B tile
    const int per = 16 * tiles_n;
    const int grp = blockIdx.x / per, rem = blockIdx.x % per;
    const int mt = grp * 16 + (rem % 16);
    const int nt = rem / 16;
    const long long bm0 = (long long)mt * 128, bn0 = (long long)nt * 128;

    const int ldr = tid >> 3;             // 0..15 base row
    const int ldh = (tid & 7) * 8;        // half col {0,8,...,56}

    auto load_stage = [&](int j) {
        __half* As = sm + (j % NSTG) * STG_H;
        __half* Bs = As + 128 * HSTR;
        const long long k0 = (long long)j * GBK;
        const __half* Ap = Ag + (bm0 + ldr) * K + k0 + ldh;
        const __half* Bp = Bg + (bn0 + ldr) * K + k0 + ldh;
        uint32_t da = s2u(As + ldr * HSTR + ldh);
        uint32_t db = s2u(Bs + ldr * HSTR + ldh);
        #pragma unroll
        for (int i = 0; i < 8; i++) {
            cpa16(da + i * 16 * HSTR * 2, Ap + (long long)i * 16 * K);
            cpa16(db + i * 16 * HSTR * 2, Bp + (long long)i * 16 * K);
        }
    };

    float acc[4][8][4];
    #pragma unroll
    for (int mi = 0; mi < 4; mi++)
        #pragma unroll
        for (int ni = 0; ni < 8; ni++)
            #pragma unroll
            for (int q = 0; q < 4; q++) acc[mi][ni][q] = 0.f;

    const int nk = K >> 6;
    load_stage(0);
    asm volatile("cp.async.commit_group;" ::: "memory");
    load_stage(1);
    asm volatile("cp.async.commit_group;" ::: "memory");

    for (int j = 0; j < nk; j++) {
        asm volatile("cp.async.wait_group 1;" ::: "memory");
        __syncthreads();
        if (j + 2 < nk) load_stage(j + 2);
        asm volatile("cp.async.commit_group;" ::: "memory");

        const __half* a = sm + (j % NSTG) * STG_H;
        const __half* b = a + 128 * HSTR;
        #pragma unroll
        for (int ks = 0; ks < 4; ks++) {
            unsigned af[4][4], bf[8][2];
            #pragma unroll
            for (int mi = 0; mi < 4; mi++) {
                const __half* p = a + (wm + mi * 16 + gid) * HSTR + ks * 16 + 2 * tig;
                af[mi][0] = *(const unsigned*)(p);
                af[mi][1] = *(const unsigned*)(p + 8 * HSTR);
                af[mi][2] = *(const unsigned*)(p + 8);
                af[mi][3] = *(const unsigned*)(p + 8 * HSTR + 8);
            }
            #pragma unroll
            for (int ni = 0; ni < 8; ni++) {
                const __half* p = b + (wn + ni * 8 + gid) * HSTR + ks * 16 + 2 * tig;
                bf[ni][0] = *(const unsigned*)(p);
                bf[ni][1] = *(const unsigned*)(p + 8);
            }
            #pragma unroll
            for (int mi = 0; mi < 4; mi++)
                #pragma unroll
                for (int ni = 0; ni < 8; ni++)
                    mma16(acc[mi][ni], af[mi], bf[ni]);
        }
        // no end-of-loop barrier needed: next iteration's post-wait barrier
        // orders stage-slot reuse (j+3's slot == j's slot, loaded after sync)
    }

    // epilogue
    #pragma unroll
    for (int mi = 0; mi < 4; mi++) {
        #pragma unroll
        for (int ni = 0; ni < 8; ni++) {
            long long row = bm0 + wm + mi * 16 + gid;
            long long col = bn0 + wn + ni * 8 + 2 * tig;
            long long i0 = row * N + col;
            long long i1 = (row + 8) * N + col;
            float v00 = acc[mi][ni][0], v01 = acc[mi][ni][1];
            float v10 = acc[mi][ni][2], v11 = acc[mi][ni][3];
            if (MODE == 1) {
                v00 = 1.f / (1.f + __expf(-v00)); v01 = 1.f / (1.f + __expf(-v01));
                v10 = 1.f / (1.f + __expf(-v10)); v11 = 1.f / (1.f + __expf(-v11));
            } else if (MODE == 3) {
                v00 += base[i0]; v01 += base[i0 + 1];
                v10 += base[i1]; v11 += base[i1 + 1];
            } else if (MODE == 4) {
                v00 = fmaf(mul[i0], v00, base[i0]);
                v01 = fmaf(mul[i0 + 1], v01, base[i0 + 1]);
                v10 = fmaf(mul[i1], v10, base[i1]);
                v11 = fmaf(mul[i1 + 1], v11, base[i1 + 1]);
            }
            if (MODE == 2) {
                __half* Og = (__half*)Ogv;
                float t00 = fmaxf(v00, 0.f), t01 = fmaxf(v01, 0.f);
                float t10 = fmaxf(v10, 0.f), t11 = fmaxf(v11, 0.f);
                *(__half2*)(Og + i0) = __floats2half2_rn(t00 * t00, t01 * t01);
                *(__half2*)(Og + i1) = __floats2half2_rn(t10 * t10, t11 * t11);
            } else {
                float* Og = (float*)Ogv;
                *(float2*)(Og + i0) = make_float2(v00, v01);
                *(float2*)(Og + i1) = make_float2(v10, v11);
            }
        }
    }
}

// ---------------------------------------------------------------------------
// Launcher
// ---------------------------------------------------------------------------
extern "C" void kernel_launch(void* const* d_in, const int* in_sizes, int n_in,
                              void* d_out, int out_size)
{
    const float* x    = (const float*)d_in[0];
    const float* tm   = (const float*)d_in[1];
    const float* st   = (const float*)d_in[2];
    const float* cm   = (const float*)d_in[3];
    const float* g1   = (const float*)d_in[4];
    const float* b1   = (const float*)d_in[5];
    const float* g2   = (const float*)d_in[6];
    const float* b2   = (const float*)d_in[7];
    const float* td   = (const float*)d_in[8];
    const float* tfst = (const float*)d_in[9];
    const float* amk  = (const float*)d_in[10];
    const float* amv  = (const float*)d_in[11];
    const float* amr  = (const float*)d_in[12];
    const float* Wk   = (const float*)d_in[13];
    const float* Wv   = (const float*)d_in[14];
    const float* Wr   = (const float*)d_in[15];
    const float* Wo   = (const float*)d_in[16];
    const float* fmk  = (const float*)d_in[17];
    const float* fmr  = (const float*)d_in[18];
    const float* Wkf  = (const float*)d_in[19];
    const float* Wrf  = (const float*)d_in[20];
    const float* Wvf  = (const float*)d_in[21];

    float* out     = (float*)d_out;
    float* out_x   = out;
    float* out_wkv = out + BTCll;
    float* out_tm  = out_wkv + (long long)B_ * C_ * 3;
    float* out_cm  = out_tm + (long long)B_ * C_;

    float* buf = nullptr;
    cudaGetSymbolAddress((void**)&buf, g_buf);
    __half* xk_h = (__half*)(buf);
    __half* xv_h = xk_h + BTCll;
    __half* xr_h = xv_h + BTCll;
    float*  kk   = buf + 3 * (BTCll / 2);
    float*  vv   = kk + BTCll;
    float*  sr   = vv + BTCll;
    __half* sy_h = (__half*)(sr + BTCll);
    __half* kf_h = sy_h + BTCll;
    __half* hW   = kf_h + BTFll;
    __half* hWk  = hW;
    __half* hWv  = hWk + ACll;
    __half* hWr  = hWv + ACll;
    __half* hWo  = hWr + ACll;
    __half* hWkf = hWo + ACll;
    __half* hWrf = hWkf + FCll;
    __half* hWvf = hWrf + ACll;

    cudaFuncSetAttribute((const void*)gemm_h<0>, cudaFuncAttributeMaxDynamicSharedMemorySize, GEMM_SMEM);
    cudaFuncSetAttribute((const void*)gemm_h<1>, cudaFuncAttributeMaxDynamicSharedMemorySize, GEMM_SMEM);
    cudaFuncSetAttribute((const void*)gemm_h<2>, cudaFuncAttributeMaxDynamicSharedMemorySize, GEMM_SMEM);
    cudaFuncSetAttribute((const void*)gemm_h<3>, cudaFuncAttributeMaxDynamicSharedMemorySize, GEMM_SMEM);
    cudaFuncSetAttribute((const void*)gemm_h<4>, cudaFuncAttributeMaxDynamicSharedMemorySize, GEMM_SMEM);

    const int M = B_ * T_;
    const int tm_ = M / 128;

    // weight fp32 -> fp16 (2 launches)
    conv_att_kernel<<<(int)(4 * ACll / 4 / 256), 256>>>(Wk, Wv, Wr, Wo, hW);
    conv_ffn_kernel<<<(int)((2 * FCll + ACll) / 4 / 256), 256>>>(Wkf, Wrf, Wvf, hWkf);

    // --- attention path ---
    ln_mix_kernel<3><<<M, 256>>>(x, tm, g1, b1, amk, amv, amr, xk_h, xv_h, xr_h, out_tm);

    gemm_h<0><<<tm_ * (A_ / 128), 128, GEMM_SMEM>>>(xk_h, hWk, kk, nullptr, nullptr, M, A_, C_, A_ / 128);
    gemm_h<0><<<tm_ * (A_ / 128), 128, GEMM_SMEM>>>(xv_h, hWv, vv, nullptr, nullptr, M, A_, C_, A_ / 128);
    gemm_h<1><<<tm_ * (A_ / 128), 128, GEMM_SMEM>>>(xr_h, hWr, sr, nullptr, nullptr, M, A_, C_, A_ / 128);

    wkv_scan_kernel<<<(B_ * A_) / 64, 64>>>(kk, vv, sr, td, tfst, st, sy_h, out_wkv);

    gemm_h<3><<<tm_ * (C_ / 128), 128, GEMM_SMEM>>>(sy_h, hWo, out_x, x, nullptr, M, C_, A_, C_ / 128);

    // --- ffn path ---
    ln_mix_kernel<2><<<M, 256>>>(out_x, cm, g2, b2, fmk, fmr, nullptr, xk_h, xr_h, nullptr, out_cm);

    gemm_h<2><<<tm_ * (FF_ / 128), 128, GEMM_SMEM>>>(xk_h, hWkf, kf_h, nullptr, nullptr, M, FF_, C_, FF_ / 128);
    gemm_h<1><<<tm_ * (C_ / 128), 128, GEMM_SMEM>>>(xr_h, hWrf, vv, nullptr, nullptr, M, C_, C_, C_ / 128);
    gemm_h<4><<<tm_ * (C_ / 128), 128, GEMM_SMEM>>>(kf_h, hWvf, out_x, out_x, vv, M, C_, FF_, C_ / 128);
}